// round 1
// baseline (speedup 1.0000x reference)
#include <cuda_runtime.h>
#include <math.h>

#define B_ 256
#define T_ 512
#define I_ 512
#define H_ 1024
#define G_ 4096   // 4*H

// ---------------- device scratch (no allocations allowed) ----------------
// pre-activations pre[t][b][j'] fp32, split into two 1 GiB halves (t<256 / t>=256)
__device__ float g_pre0[(size_t)256 * B_ * G_];
__device__ float g_pre1[(size_t)256 * B_ * G_];
// double-buffered hidden state
__device__ float g_h[2][B_ * H_];
// gate-interleaved (permuted) weights and bias: j' = h_idx*4 + gate
__device__ float g_Wip[G_ * I_];
__device__ float g_Whp[G_ * H_];
__device__ float g_biasp[G_];

// ---------------- permutation + init ----------------
__global__ void permute_init_k(const float* __restrict__ Wi,
                               const float* __restrict__ Wh,
                               const float* __restrict__ bi,
                               const float* __restrict__ bh) {
    int stride = gridDim.x * blockDim.x;
    int tid0 = blockIdx.x * blockDim.x + threadIdx.x;
    // W_hh permute: [4096 x 1024]
    for (int idx = tid0; idx < G_ * H_; idx += stride) {
        int jp = idx / H_, i = idx % H_;
        int gate = jp & 3, hh = jp >> 2;
        g_Whp[idx] = Wh[(size_t)(gate * H_ + hh) * H_ + i];
    }
    // W_ih permute: [4096 x 512]
    for (int idx = tid0; idx < G_ * I_; idx += stride) {
        int jp = idx / I_, i = idx % I_;
        int gate = jp & 3, hh = jp >> 2;
        g_Wip[idx] = Wi[(size_t)(gate * H_ + hh) * I_ + i];
    }
    // bias permute: b_ih + b_hh
    for (int idx = tid0; idx < G_; idx += stride) {
        int gate = idx & 3, hh = idx >> 2;
        int j = gate * H_ + hh;
        g_biasp[idx] = bi[j] + bh[j];
    }
    // h0 = 0
    for (int idx = tid0; idx < B_ * H_; idx += stride) {
        g_h[0][idx] = 0.0f;
    }
}

// ---------------- input GEMM: pre[t][b][j'] = x[b][t][:] . Wip[j'][:] + biasp[j'] ----------------
__global__ void __launch_bounds__(256) pregemm_k(const float* __restrict__ x) {
    __shared__ float As[16][64];
    __shared__ float Bs[16][64];

    const int t  = blockIdx.z;
    const int rb = blockIdx.x * 64;   // batch tile
    const int cb = blockIdx.y * 64;   // j' tile
    const int tid = threadIdx.x;
    const int tx = tid & 15, ty = tid >> 4;
    const int lr = tid >> 2;          // 0..63
    const int kq = (tid & 3) * 4;     // 0,4,8,12

    float acc[4][4] = {};

    const float* aptr = x + ((size_t)(rb + lr) * T_ + t) * I_ + kq;
    const float* bptr = g_Wip + (size_t)(cb + lr) * I_ + kq;

    for (int k0 = 0; k0 < I_; k0 += 16) {
        float4 av = *(const float4*)(aptr + k0);
        float4 bv = *(const float4*)(bptr + k0);
        As[kq + 0][lr] = av.x; As[kq + 1][lr] = av.y;
        As[kq + 2][lr] = av.z; As[kq + 3][lr] = av.w;
        Bs[kq + 0][lr] = bv.x; Bs[kq + 1][lr] = bv.y;
        Bs[kq + 2][lr] = bv.z; Bs[kq + 3][lr] = bv.w;
        __syncthreads();
#pragma unroll
        for (int k = 0; k < 16; k++) {
            float4 a4 = *(const float4*)&As[k][ty * 4];
            float4 b4 = *(const float4*)&Bs[k][tx * 4];
            float ar[4] = {a4.x, a4.y, a4.z, a4.w};
            float br[4] = {b4.x, b4.y, b4.z, b4.w};
#pragma unroll
            for (int i = 0; i < 4; i++)
#pragma unroll
                for (int j = 0; j < 4; j++)
                    acc[i][j] += ar[i] * br[j];
        }
        __syncthreads();
    }

    float* preh = (t < 256 ? g_pre0 : g_pre1);
    const size_t tb = (size_t)(t & 255) * B_ * G_;
    float4 bias = *(const float4*)&g_biasp[cb + tx * 4];
#pragma unroll
    for (int i = 0; i < 4; i++) {
        float4 v;
        v.x = acc[i][0] + bias.x;
        v.y = acc[i][1] + bias.y;
        v.z = acc[i][2] + bias.z;
        v.w = acc[i][3] + bias.w;
        *(float4*)&preh[tb + (size_t)(rb + ty * 4 + i) * G_ + cb + tx * 4] = v;
    }
}

// ---------------- one LSTM step: gates = pre[t] + h_in . Whp^T ; update c, h ----------------
__device__ __forceinline__ float sigm(float v) { return 1.0f / (1.0f + expf(-v)); }

__global__ void __launch_bounds__(256) step_k(float* __restrict__ c, int t) {
    __shared__ float As[16][64];
    __shared__ float Bs[16][64];
    __shared__ float Gs[64][64];

    const float* __restrict__ h_in  = g_h[t & 1];
    float* __restrict__       h_out = g_h[(t & 1) ^ 1];

    const int rb = blockIdx.x * 64;   // batch tile
    const int cb = blockIdx.y * 64;   // j' tile (16 h-indices x 4 gates)
    const int tid = threadIdx.x;
    const int tx = tid & 15, ty = tid >> 4;
    const int lr = tid >> 2;
    const int kq = (tid & 3) * 4;

    float acc[4][4] = {};

    const float* aptr = h_in + (size_t)(rb + lr) * H_ + kq;
    const float* bptr = g_Whp + (size_t)(cb + lr) * H_ + kq;

    for (int k0 = 0; k0 < H_; k0 += 16) {
        float4 av = *(const float4*)(aptr + k0);
        float4 bv = *(const float4*)(bptr + k0);
        As[kq + 0][lr] = av.x; As[kq + 1][lr] = av.y;
        As[kq + 2][lr] = av.z; As[kq + 3][lr] = av.w;
        Bs[kq + 0][lr] = bv.x; Bs[kq + 1][lr] = bv.y;
        Bs[kq + 2][lr] = bv.z; Bs[kq + 3][lr] = bv.w;
        __syncthreads();
#pragma unroll
        for (int k = 0; k < 16; k++) {
            float4 a4 = *(const float4*)&As[k][ty * 4];
            float4 b4 = *(const float4*)&Bs[k][tx * 4];
            float ar[4] = {a4.x, a4.y, a4.z, a4.w};
            float br[4] = {b4.x, b4.y, b4.z, b4.w};
#pragma unroll
            for (int i = 0; i < 4; i++)
#pragma unroll
                for (int j = 0; j < 4; j++)
                    acc[i][j] += ar[i] * br[j];
        }
        __syncthreads();
    }

    // add pre-activations and park gates in shared
    const float* preh = (t < 256 ? g_pre0 : g_pre1);
    const size_t tb = (size_t)(t & 255) * B_ * G_;
#pragma unroll
    for (int i = 0; i < 4; i++) {
        float4 p = *(const float4*)&preh[tb + (size_t)(rb + ty * 4 + i) * G_ + cb + tx * 4];
        Gs[ty * 4 + i][tx * 4 + 0] = acc[i][0] + p.x;
        Gs[ty * 4 + i][tx * 4 + 1] = acc[i][1] + p.y;
        Gs[ty * 4 + i][tx * 4 + 2] = acc[i][2] + p.z;
        Gs[ty * 4 + i][tx * 4 + 3] = acc[i][3] + p.w;
    }
    __syncthreads();

    // activation + state update: 64 rows x 16 h-indices, gates interleaved i,f,g,o
    const int hb = cb >> 2;
    for (int it = tid; it < 64 * 16; it += 256) {
        int r = it >> 4, hh = it & 15;
        float4 gv = *(const float4*)&Gs[r][hh * 4];
        float iv = sigm(gv.x);
        float fv = sigm(gv.y);
        float gg = tanhf(gv.z);
        float ov = sigm(gv.w);
        size_t idx = (size_t)(rb + r) * H_ + hb + hh;
        float cn = fv * c[idx] + iv * gg;
        c[idx] = cn;
        h_out[idx] = ov * tanhf(cn);
    }
}

// ---------------- launch ----------------
extern "C" void kernel_launch(void* const* d_in, const int* in_sizes, int n_in,
                              void* d_out, int out_size) {
    const float* x  = (const float*)d_in[0];
    const float* Wi = (const float*)d_in[1];
    const float* Wh = (const float*)d_in[2];
    const float* bi = (const float*)d_in[3];
    const float* bh = (const float*)d_in[4];
    const float* c0 = (const float*)d_in[5];
    float* c = (float*)d_out;

    // c starts as c0 (output buffer doubles as the live cell state)
    cudaMemcpyAsync(c, c0, sizeof(float) * B_ * H_, cudaMemcpyDeviceToDevice);

    permute_init_k<<<512, 256>>>(Wi, Wh, bi, bh);

    // pre[t][b][j'] for all timesteps in one big GEMM
    pregemm_k<<<dim3(B_ / 64, G_ / 64, T_), 256>>>(x);

    // sequential recurrence
    for (int t = 0; t < T_; t++) {
        step_k<<<dim3(B_ / 64, G_ / 64), 256>>>(c, t);
    }
}

// round 3
// speedup vs baseline: 2.4722x; 2.4722x over previous
#include <cuda_runtime.h>
#include <cuda_bf16.h>
#include <cstdint>
#include <math.h>

#define B_ 256
#define T_ 512
#define I_ 512
#define H_ 1024
#define G_ 4096   // 4*H

// ==================== device scratch (no allocations allowed) ====================
__device__ float g_pre0[(size_t)256 * B_ * G_];
__device__ float g_pre1[(size_t)256 * B_ * G_];
__device__ __align__(128) __nv_bfloat16 g_x_hi[(size_t)B_ * T_ * I_];
__device__ __align__(128) __nv_bfloat16 g_x_lo[(size_t)B_ * T_ * I_];
__device__ __align__(128) __nv_bfloat16 g_h_hi[2][B_ * H_];
__device__ __align__(128) __nv_bfloat16 g_h_lo[2][B_ * H_];
__device__ __align__(128) __nv_bfloat16 g_Wip_hi[G_ * I_];
__device__ __align__(128) __nv_bfloat16 g_Wip_lo[G_ * I_];
__device__ __align__(128) __nv_bfloat16 g_Whp_hi[G_ * H_];
__device__ __align__(128) __nv_bfloat16 g_Whp_lo[G_ * H_];
__device__ float g_biasp[G_];

// ==================== PTX helpers (plain sm_103 feature set) ====================
__device__ __forceinline__ uint32_t smem_u32(const void* p) {
    uint32_t a;
    asm("{ .reg .u64 t; cvta.to.shared.u64 t, %1; cvt.u32.u64 %0, t; }" : "=r"(a) : "l"(p));
    return a;
}
#define CP16(dst_u32, src_ptr) \
    asm volatile("cp.async.cg.shared.global [%0], [%1], 16;" :: "r"(dst_u32), "l"(src_ptr) : "memory")
#define CP_COMMIT() asm volatile("cp.async.commit_group;" ::: "memory")
#define CP_WAIT1()  asm volatile("cp.async.wait_group 1;" ::: "memory")
#define CP_WAIT0()  asm volatile("cp.async.wait_group 0;" ::: "memory")
#define LDSM4(r0, r1, r2, r3, addr) \
    asm volatile("ldmatrix.sync.aligned.m8n8.x4.shared.b16 {%0,%1,%2,%3}, [%4];" \
        : "=r"(r0), "=r"(r1), "=r"(r2), "=r"(r3) : "r"(addr))
#define MMA_BF16(c, a, b) \
    asm volatile("mma.sync.aligned.m16n8k16.row.col.f32.bf16.bf16.f32 " \
        "{%0,%1,%2,%3}, {%4,%5,%6,%7}, {%8,%9}, {%0,%1,%2,%3};" \
        : "+f"((c)[0]), "+f"((c)[1]), "+f"((c)[2]), "+f"((c)[3]) \
        : "r"((a)[0]), "r"((a)[1]), "r"((a)[2]), "r"((a)[3]), "r"((b)[0]), "r"((b)[1]))

// ==================== smem layout ====================
// stage: A_hi[128][40] A_lo[128][40] B_hi[64][40] B_lo[64][40] (bf16, 40 = 32+8 pad)
#define ASTRIDE_B  80                 // bytes per smem row
#define AH_OFF     0
#define AL_OFF     10240              // 128*80
#define BH_OFF     20480
#define BL_OFF     25600              // +64*80
#define STAGE_B    30720
#define SMEM_BYTES (2 * STAGE_B)      // 61440

// ==================== stage loader (gmem -> smem via cp.async) ====================
// a_*: base of 128 A rows at this chunk's k-offset; b_*: base of 64 B rows.
__device__ __forceinline__ void load_stage(uint32_t sb,
                                           const __nv_bfloat16* a_hi, const __nv_bfloat16* a_lo,
                                           const __nv_bfloat16* b_hi, const __nv_bfloat16* b_lo,
                                           int a_stride, int b_stride, int tid) {
#pragma unroll
    for (int i = 0; i < 2; i++) {
        int idx = tid + i * 256;          // 0..511
        int r = idx >> 2, u = idx & 3;
        uint32_t so = (uint32_t)(r * ASTRIDE_B + u * 16);
        CP16(sb + AH_OFF + so, a_hi + (size_t)r * a_stride + u * 8);
        CP16(sb + AL_OFF + so, a_lo + (size_t)r * a_stride + u * 8);
    }
    {
        int r = tid >> 2, u = tid & 3;    // 0..255 covers 64 rows x 4 units
        uint32_t so = (uint32_t)(r * ASTRIDE_B + u * 16);
        CP16(sb + BH_OFF + so, b_hi + (size_t)r * b_stride + u * 8);
        CP16(sb + BL_OFF + so, b_lo + (size_t)r * b_stride + u * 8);
    }
}

// ==================== warp MMA core: one k32 chunk, 3 split terms ====================
__device__ __forceinline__ void compute_chunk(uint32_t sb, int wid, int lane,
                                              float acc[2][4][4]) {
    const int wm = (wid >> 1) * 32;       // warp M base within 128
    const int wn = (wid & 1) * 32;        // warp N base within 64
    const uint32_t a_row  = (uint32_t)(lane & 15);
    const uint32_t a_koff = (uint32_t)((lane >> 4) * 16);          // bytes
    const uint32_t b_row  = (uint32_t)(((lane >> 4) << 3) + (lane & 7));
    const uint32_t b_koff = (uint32_t)(((lane >> 3) & 1) * 16);    // bytes

#pragma unroll
    for (int ks = 0; ks < 2; ks++) {
        const uint32_t kb = (uint32_t)(ks * 32);
        uint32_t aH[2][4], aL[2][4], bH[4][2], bL[4][2];
#pragma unroll
        for (int mt = 0; mt < 2; mt++) {
            uint32_t ad = sb + AH_OFF + (wm + mt * 16 + a_row) * ASTRIDE_B + kb + a_koff;
            LDSM4(aH[mt][0], aH[mt][1], aH[mt][2], aH[mt][3], ad);
            LDSM4(aL[mt][0], aL[mt][1], aL[mt][2], aL[mt][3], ad + (AL_OFF - AH_OFF));
        }
#pragma unroll
        for (int p = 0; p < 2; p++) {
            uint32_t bd = sb + BH_OFF + (wn + p * 16 + b_row) * ASTRIDE_B + kb + b_koff;
            LDSM4(bH[2 * p][0], bH[2 * p][1], bH[2 * p + 1][0], bH[2 * p + 1][1], bd);
            LDSM4(bL[2 * p][0], bL[2 * p][1], bL[2 * p + 1][0], bL[2 * p + 1][1],
                  bd + (BL_OFF - BH_OFF));
        }
#pragma unroll
        for (int mt = 0; mt < 2; mt++)
#pragma unroll
            for (int nt = 0; nt < 4; nt++) {
                MMA_BF16(acc[mt][nt], aH[mt], bH[nt]);
                MMA_BF16(acc[mt][nt], aH[mt], bL[nt]);
                MMA_BF16(acc[mt][nt], aL[mt], bH[nt]);
            }
    }
}

// ==================== init: permute + split weights, bias, h0 ====================
__global__ void permute_init_k(const float* __restrict__ Wi,
                               const float* __restrict__ Wh,
                               const float* __restrict__ bi,
                               const float* __restrict__ bh) {
    int stride = gridDim.x * blockDim.x;
    int tid0 = blockIdx.x * blockDim.x + threadIdx.x;
    for (int idx = tid0; idx < G_ * H_; idx += stride) {
        int jp = idx / H_, i = idx % H_;
        int gate = jp & 3, hh = jp >> 2;
        float w = Wh[(size_t)(gate * H_ + hh) * H_ + i];
        __nv_bfloat16 hi = __float2bfloat16_rn(w);
        g_Whp_hi[idx] = hi;
        g_Whp_lo[idx] = __float2bfloat16_rn(w - __bfloat162float(hi));
    }
    for (int idx = tid0; idx < G_ * I_; idx += stride) {
        int jp = idx / I_, i = idx % I_;
        int gate = jp & 3, hh = jp >> 2;
        float w = Wi[(size_t)(gate * H_ + hh) * I_ + i];
        __nv_bfloat16 hi = __float2bfloat16_rn(w);
        g_Wip_hi[idx] = hi;
        g_Wip_lo[idx] = __float2bfloat16_rn(w - __bfloat162float(hi));
    }
    for (int idx = tid0; idx < G_; idx += stride) {
        int gate = idx & 3, hh = idx >> 2;
        int j = gate * H_ + hh;
        g_biasp[idx] = bi[j] + bh[j];
    }
    for (int idx = tid0; idx < B_ * H_; idx += stride) {
        g_h_hi[0][idx] = __float2bfloat16_rn(0.0f);
        g_h_lo[0][idx] = __float2bfloat16_rn(0.0f);
    }
}

// ==================== split x into bf16 hi/lo ====================
__global__ void split_x_k(const float* __restrict__ x) {
    size_t n4 = (size_t)B_ * T_ * I_ / 4;
    size_t stride = (size_t)gridDim.x * blockDim.x;
    for (size_t i = blockIdx.x * blockDim.x + threadIdx.x; i < n4; i += stride) {
        float4 v = ((const float4*)x)[i];
        __nv_bfloat16 h0 = __float2bfloat16_rn(v.x);
        __nv_bfloat16 h1 = __float2bfloat16_rn(v.y);
        __nv_bfloat16 h2 = __float2bfloat16_rn(v.z);
        __nv_bfloat16 h3 = __float2bfloat16_rn(v.w);
        __nv_bfloat162* dhi = (__nv_bfloat162*)(g_x_hi + i * 4);
        __nv_bfloat162* dlo = (__nv_bfloat162*)(g_x_lo + i * 4);
        dhi[0] = __nv_bfloat162(h0, h1);
        dhi[1] = __nv_bfloat162(h2, h3);
        dlo[0] = __nv_bfloat162(__float2bfloat16_rn(v.x - __bfloat162float(h0)),
                                __float2bfloat16_rn(v.y - __bfloat162float(h1)));
        dlo[1] = __nv_bfloat162(__float2bfloat16_rn(v.z - __bfloat162float(h2)),
                                __float2bfloat16_rn(v.w - __bfloat162float(h3)));
    }
}

// ==================== pregemm: pre[t][b][j'] = x . WipT + bias (HMMA, split) ====================
__global__ void __launch_bounds__(256) pregemm_k() {
    extern __shared__ char smem[];
    const uint32_t sm0 = smem_u32(smem);
    const int tid = threadIdx.x;
    const int wid = tid >> 5, lane = tid & 31;
    const int mb = blockIdx.x * 128;      // m = b*T + t
    const int cb = blockIdx.y * 64;       // j'

    const __nv_bfloat16* a_hi = g_x_hi + (size_t)mb * I_;
    const __nv_bfloat16* a_lo = g_x_lo + (size_t)mb * I_;
    const __nv_bfloat16* b_hi = g_Wip_hi + (size_t)cb * I_;
    const __nv_bfloat16* b_lo = g_Wip_lo + (size_t)cb * I_;

    float acc[2][4][4] = {};

    load_stage(sm0, a_hi, a_lo, b_hi, b_lo, I_, I_, tid);
    CP_COMMIT();
#pragma unroll 1
    for (int ch = 0; ch < 16; ch++) {
        if (ch + 1 < 16) {
            load_stage(sm0 + ((ch + 1) & 1) * STAGE_B,
                       a_hi + (ch + 1) * 32, a_lo + (ch + 1) * 32,
                       b_hi + (ch + 1) * 32, b_lo + (ch + 1) * 32, I_, I_, tid);
            CP_COMMIT();
            CP_WAIT1();
        } else {
            CP_WAIT0();
        }
        __syncthreads();
        compute_chunk(sm0 + (ch & 1) * STAGE_B, wid, lane, acc);
        __syncthreads();
    }

    // epilogue: + bias, scatter to pre[t][b][j']
    const int wm = (wid >> 1) * 32;
    const int wn = (wid & 1) * 32;
    const int qr = lane >> 2, qc = 2 * (lane & 3);
#pragma unroll
    for (int mt = 0; mt < 2; mt++) {
#pragma unroll
        for (int half = 0; half < 2; half++) {
            int r = wm + mt * 16 + qr + half * 8;
            int m = mb + r;
            int b = m >> 9, tt = m & 511;
            float* preh = (tt < 256 ? g_pre0 : g_pre1);
            float* dst = preh + (size_t)(tt & 255) * B_ * G_ + (size_t)b * G_ + cb;
#pragma unroll
            for (int nt = 0; nt < 4; nt++) {
                int col = wn + nt * 8 + qc;
                dst[col]     = acc[mt][nt][half * 2 + 0] + g_biasp[cb + col];
                dst[col + 1] = acc[mt][nt][half * 2 + 1] + g_biasp[cb + col + 1];
            }
        }
    }
}

// ==================== one LSTM step (HMMA, split, fused epilogue) ====================
__device__ __forceinline__ float sigm(float v) { return 1.0f / (1.0f + expf(-v)); }

__global__ void __launch_bounds__(256) step_k(float* __restrict__ c, int t) {
    extern __shared__ char smem[];
    const uint32_t sm0 = smem_u32(smem);
    const int tid = threadIdx.x;
    const int wid = tid >> 5, lane = tid & 31;
    const int rb = blockIdx.x * 128;      // batch tile
    const int cb = blockIdx.y * 64;       // j' tile
    const int hb = cb >> 2;

    const __nv_bfloat16* a_hi = g_h_hi[t & 1] + (size_t)rb * H_;
    const __nv_bfloat16* a_lo = g_h_lo[t & 1] + (size_t)rb * H_;
    const __nv_bfloat16* b_hi = g_Whp_hi + (size_t)cb * H_;
    const __nv_bfloat16* b_lo = g_Whp_lo + (size_t)cb * H_;
    __nv_bfloat16* __restrict__ hout_hi = g_h_hi[(t & 1) ^ 1];
    __nv_bfloat16* __restrict__ hout_lo = g_h_lo[(t & 1) ^ 1];

    float acc[2][4][4] = {};

    load_stage(sm0, a_hi, a_lo, b_hi, b_lo, H_, H_, tid);
    CP_COMMIT();
#pragma unroll 1
    for (int ch = 0; ch < 32; ch++) {
        if (ch + 1 < 32) {
            load_stage(sm0 + ((ch + 1) & 1) * STAGE_B,
                       a_hi + (ch + 1) * 32, a_lo + (ch + 1) * 32,
                       b_hi + (ch + 1) * 32, b_lo + (ch + 1) * 32, H_, H_, tid);
            CP_COMMIT();
            CP_WAIT1();
        } else {
            CP_WAIT0();
        }
        __syncthreads();
        compute_chunk(sm0 + (ch & 1) * STAGE_B, wid, lane, acc);
        __syncthreads();
    }

    // park gates in smem (fp32, stride 68 to dodge conflicts)
    float* Gs = (float*)smem;
    const int wm = (wid >> 1) * 32;
    const int wn = (wid & 1) * 32;
    const int qr = lane >> 2, qc = 2 * (lane & 3);
#pragma unroll
    for (int mt = 0; mt < 2; mt++)
#pragma unroll
        for (int nt = 0; nt < 4; nt++) {
            int r0 = wm + mt * 16 + qr;
            int cc = wn + nt * 8 + qc;
            Gs[r0 * 68 + cc]           = acc[mt][nt][0];
            Gs[r0 * 68 + cc + 1]       = acc[mt][nt][1];
            Gs[(r0 + 8) * 68 + cc]     = acc[mt][nt][2];
            Gs[(r0 + 8) * 68 + cc + 1] = acc[mt][nt][3];
        }
    __syncthreads();

    // activations + state update (gate-interleaved: j' = 4*hh + {i,f,g,o})
    const float* preh = (t < 256 ? g_pre0 : g_pre1);
    const float* prebase = preh + (size_t)(t & 255) * B_ * G_;
#pragma unroll
    for (int it = tid; it < 128 * 16; it += 256) {
        int r = it >> 4, hh = it & 15;
        float4 g = *(const float4*)&Gs[r * 68 + hh * 4];
        float4 p = *(const float4*)(prebase + (size_t)(rb + r) * G_ + cb + hh * 4);
        float iv = sigm(g.x + p.x);
        float fv = sigm(g.y + p.y);
        float gv = tanhf(g.z + p.z);
        float ov = sigm(g.w + p.w);
        size_t idx = (size_t)(rb + r) * H_ + hb + hh;
        float cn = fv * c[idx] + iv * gv;
        c[idx] = cn;
        float hn = ov * tanhf(cn);
        __nv_bfloat16 hi = __float2bfloat16_rn(hn);
        hout_hi[idx] = hi;
        hout_lo[idx] = __float2bfloat16_rn(hn - __bfloat162float(hi));
    }
}

// ==================== launch ====================
extern "C" void kernel_launch(void* const* d_in, const int* in_sizes, int n_in,
                              void* d_out, int out_size) {
    const float* x  = (const float*)d_in[0];
    const float* Wi = (const float*)d_in[1];
    const float* Wh = (const float*)d_in[2];
    const float* bi = (const float*)d_in[3];
    const float* bh = (const float*)d_in[4];
    const float* c0 = (const float*)d_in[5];
    float* c = (float*)d_out;

    static bool attr_set = false;
    if (!attr_set) {
        cudaFuncSetAttribute(pregemm_k, cudaFuncAttributeMaxDynamicSharedMemorySize, SMEM_BYTES);
        cudaFuncSetAttribute(step_k,    cudaFuncAttributeMaxDynamicSharedMemorySize, SMEM_BYTES);
        attr_set = true;
    }

    cudaMemcpyAsync(c, c0, sizeof(float) * B_ * H_, cudaMemcpyDeviceToDevice);

    split_x_k<<<4096, 256>>>(x);
    permute_init_k<<<512, 256>>>(Wi, Wh, bi, bh);

    pregemm_k<<<dim3((B_ * T_) / 128, G_ / 64), 256, SMEM_BYTES>>>();

    for (int t = 0; t < T_; t++) {
        step_k<<<dim3(B_ / 128, G_ / 64), 256, SMEM_BYTES>>>(c, t);
    }
}

// round 4
// speedup vs baseline: 2.8158x; 1.1390x over previous
#include <cuda_runtime.h>
#include <cuda_bf16.h>
#include <cstdint>
#include <math.h>

#define B_ 256
#define T_ 512
#define I_ 512
#define H_ 1024
#define G_ 4096   // 4*H

// ==================== device scratch (no allocations allowed) ====================
__device__ float g_pre0[(size_t)256 * B_ * G_];
__device__ float g_pre1[(size_t)256 * B_ * G_];
__device__ __align__(128) __nv_bfloat16 g_x_hi[(size_t)B_ * T_ * I_];
__device__ __align__(128) __nv_bfloat16 g_x_lo[(size_t)B_ * T_ * I_];
__device__ __align__(128) __nv_bfloat16 g_h_hi[2][B_ * H_];
__device__ __align__(128) __nv_bfloat16 g_h_lo[2][B_ * H_];
__device__ __align__(128) __nv_bfloat16 g_Wip_hi[G_ * I_];
__device__ __align__(128) __nv_bfloat16 g_Wip_lo[G_ * I_];
__device__ __align__(128) __nv_bfloat16 g_Whp_hi[G_ * H_];
__device__ __align__(128) __nv_bfloat16 g_Whp_lo[G_ * H_];
__device__ float g_biasp[G_];

// ==================== PTX helpers (plain sm_103 feature set) ====================
__device__ __forceinline__ uint32_t smem_u32(const void* p) {
    uint32_t a;
    asm("{ .reg .u64 t; cvta.to.shared.u64 t, %1; cvt.u32.u64 %0, t; }" : "=r"(a) : "l"(p));
    return a;
}
#define CP16(dst_u32, src_ptr) \
    asm volatile("cp.async.cg.shared.global [%0], [%1], 16;" :: "r"(dst_u32), "l"(src_ptr) : "memory")
#define CP_COMMIT() asm volatile("cp.async.commit_group;" ::: "memory")
#define CP_WAIT2()  asm volatile("cp.async.wait_group 2;" ::: "memory")
#define LDSM4(r0, r1, r2, r3, addr) \
    asm volatile("ldmatrix.sync.aligned.m8n8.x4.shared.b16 {%0,%1,%2,%3}, [%4];" \
        : "=r"(r0), "=r"(r1), "=r"(r2), "=r"(r3) : "r"(addr))
#define MMA_BF16(c, a, b) \
    asm volatile("mma.sync.aligned.m16n8k16.row.col.f32.bf16.bf16.f32 " \
        "{%0,%1,%2,%3}, {%4,%5,%6,%7}, {%8,%9}, {%0,%1,%2,%3};" \
        : "+f"((c)[0]), "+f"((c)[1]), "+f"((c)[2]), "+f"((c)[3]) \
        : "r"((a)[0]), "r"((a)[1]), "r"((a)[2]), "r"((a)[3]), "r"((b)[0]), "r"((b)[1]))

// ==================== smem layout ====================
// stage: A_hi[128][40] A_lo[128][40] B_hi[64][40] B_lo[64][40] (bf16, 40 = 32+8 pad)
#define ASTRIDE_B  80                 // bytes per smem row
#define AH_OFF     0
#define AL_OFF     10240              // 128*80
#define BH_OFF     20480
#define BL_OFF     25600
#define STAGE_B    30720
#define NSTAGE     4
#define SM_PRE     (NSTAGE * STAGE_B)         // 122880: pre tile 128x64 fp32 (32768 B)
#define SM_C       (SM_PRE + 32768)           // 155648: c tile 128x16 fp32 (8192 B)
#define SMEM_BYTES (SM_C + 8192)              // 163840

// ==================== stage loader (gmem -> smem via cp.async) ====================
__device__ __forceinline__ void load_stage(uint32_t sb,
                                           const __nv_bfloat16* a_hi, const __nv_bfloat16* a_lo,
                                           const __nv_bfloat16* b_hi, const __nv_bfloat16* b_lo,
                                           int a_stride, int b_stride, int tid) {
#pragma unroll
    for (int i = 0; i < 2; i++) {
        int idx = tid + i * 256;          // 0..511 -> 128 rows x 4 units
        int r = idx >> 2, u = idx & 3;
        uint32_t so = (uint32_t)(r * ASTRIDE_B + u * 16);
        CP16(sb + AH_OFF + so, a_hi + (size_t)r * a_stride + u * 8);
        CP16(sb + AL_OFF + so, a_lo + (size_t)r * a_stride + u * 8);
    }
    {
        int r = tid >> 2, u = tid & 3;    // 64 rows x 4 units
        uint32_t so = (uint32_t)(r * ASTRIDE_B + u * 16);
        CP16(sb + BH_OFF + so, b_hi + (size_t)r * b_stride + u * 8);
        CP16(sb + BL_OFF + so, b_lo + (size_t)r * b_stride + u * 8);
    }
}

// ==================== warp MMA core: one k32 chunk, 3 split terms ====================
__device__ __forceinline__ void compute_chunk(uint32_t sb, int wid, int lane,
                                              float acc[2][4][4]) {
    const int wm = (wid >> 1) * 32;
    const int wn = (wid & 1) * 32;
    const uint32_t a_row  = (uint32_t)(lane & 15);
    const uint32_t a_koff = (uint32_t)((lane >> 4) * 16);
    const uint32_t b_row  = (uint32_t)(((lane >> 4) << 3) + (lane & 7));
    const uint32_t b_koff = (uint32_t)(((lane >> 3) & 1) * 16);

#pragma unroll
    for (int ks = 0; ks < 2; ks++) {
        const uint32_t kb = (uint32_t)(ks * 32);
        uint32_t aH[2][4], aL[2][4], bH[4][2], bL[4][2];
#pragma unroll
        for (int mt = 0; mt < 2; mt++) {
            uint32_t ad = sb + AH_OFF + (wm + mt * 16 + a_row) * ASTRIDE_B + kb + a_koff;
            LDSM4(aH[mt][0], aH[mt][1], aH[mt][2], aH[mt][3], ad);
            LDSM4(aL[mt][0], aL[mt][1], aL[mt][2], aL[mt][3], ad + (AL_OFF - AH_OFF));
        }
#pragma unroll
        for (int p = 0; p < 2; p++) {
            uint32_t bd = sb + BH_OFF + (wn + p * 16 + b_row) * ASTRIDE_B + kb + b_koff;
            LDSM4(bH[2 * p][0], bH[2 * p][1], bH[2 * p + 1][0], bH[2 * p + 1][1], bd);
            LDSM4(bL[2 * p][0], bL[2 * p][1], bL[2 * p + 1][0], bL[2 * p + 1][1],
                  bd + (BL_OFF - BH_OFF));
        }
#pragma unroll
        for (int mt = 0; mt < 2; mt++)
#pragma unroll
            for (int nt = 0; nt < 4; nt++) {
                MMA_BF16(acc[mt][nt], aH[mt], bH[nt]);
                MMA_BF16(acc[mt][nt], aH[mt], bL[nt]);
                MMA_BF16(acc[mt][nt], aL[mt], bH[nt]);
            }
    }
}

// ==================== init: permute + split weights, bias, h0 ====================
__global__ void permute_init_k(const float* __restrict__ Wi,
                               const float* __restrict__ Wh,
                               const float* __restrict__ bi,
                               const float* __restrict__ bh) {
    int stride = gridDim.x * blockDim.x;
    int tid0 = blockIdx.x * blockDim.x + threadIdx.x;
    for (int idx = tid0; idx < G_ * H_; idx += stride) {
        int jp = idx / H_, i = idx % H_;
        int gate = jp & 3, hh = jp >> 2;
        float w = Wh[(size_t)(gate * H_ + hh) * H_ + i];
        __nv_bfloat16 hi = __float2bfloat16_rn(w);
        g_Whp_hi[idx] = hi;
        g_Whp_lo[idx] = __float2bfloat16_rn(w - __bfloat162float(hi));
    }
    for (int idx = tid0; idx < G_ * I_; idx += stride) {
        int jp = idx / I_, i = idx % I_;
        int gate = jp & 3, hh = jp >> 2;
        float w = Wi[(size_t)(gate * H_ + hh) * I_ + i];
        __nv_bfloat16 hi = __float2bfloat16_rn(w);
        g_Wip_hi[idx] = hi;
        g_Wip_lo[idx] = __float2bfloat16_rn(w - __bfloat162float(hi));
    }
    for (int idx = tid0; idx < G_; idx += stride) {
        int gate = idx & 3, hh = idx >> 2;
        int j = gate * H_ + hh;
        g_biasp[idx] = bi[j] + bh[j];
    }
    for (int idx = tid0; idx < B_ * H_; idx += stride) {
        g_h_hi[0][idx] = __float2bfloat16_rn(0.0f);
        g_h_lo[0][idx] = __float2bfloat16_rn(0.0f);
    }
}

// ==================== split x into bf16 hi/lo ====================
__global__ void split_x_k(const float* __restrict__ x) {
    size_t n4 = (size_t)B_ * T_ * I_ / 4;
    size_t stride = (size_t)gridDim.x * blockDim.x;
    for (size_t i = blockIdx.x * blockDim.x + threadIdx.x; i < n4; i += stride) {
        float4 v = ((const float4*)x)[i];
        __nv_bfloat16 h0 = __float2bfloat16_rn(v.x);
        __nv_bfloat16 h1 = __float2bfloat16_rn(v.y);
        __nv_bfloat16 h2 = __float2bfloat16_rn(v.z);
        __nv_bfloat16 h3 = __float2bfloat16_rn(v.w);
        __nv_bfloat162* dhi = (__nv_bfloat162*)(g_x_hi + i * 4);
        __nv_bfloat162* dlo = (__nv_bfloat162*)(g_x_lo + i * 4);
        dhi[0] = __nv_bfloat162(h0, h1);
        dhi[1] = __nv_bfloat162(h2, h3);
        dlo[0] = __nv_bfloat162(__float2bfloat16_rn(v.x - __bfloat162float(h0)),
                                __float2bfloat16_rn(v.y - __bfloat162float(h1)));
        dlo[1] = __nv_bfloat162(__float2bfloat16_rn(v.z - __bfloat162float(h2)),
                                __float2bfloat16_rn(v.w - __bfloat162float(h3)));
    }
}

// ==================== pregemm: pre[t][b][j'] = x . WipT + bias (HMMA, split) ====================
__global__ void __launch_bounds__(256, 1) pregemm_k() {
    extern __shared__ char smem[];
    const uint32_t sm0 = smem_u32(smem);
    const int tid = threadIdx.x;
    const int wid = tid >> 5, lane = tid & 31;
    const int mb = blockIdx.x * 128;
    const int cb = blockIdx.y * 64;

    const __nv_bfloat16* a_hi = g_x_hi + (size_t)mb * I_;
    const __nv_bfloat16* a_lo = g_x_lo + (size_t)mb * I_;
    const __nv_bfloat16* b_hi = g_Wip_hi + (size_t)cb * I_;
    const __nv_bfloat16* b_lo = g_Wip_lo + (size_t)cb * I_;

    float acc[2][4][4] = {};

    // prologue: 3 stages in flight
#pragma unroll
    for (int s = 0; s < 3; s++) {
        load_stage(sm0 + s * STAGE_B, a_hi + s * 32, a_lo + s * 32,
                   b_hi + s * 32, b_lo + s * 32, I_, I_, tid);
        CP_COMMIT();
    }
#pragma unroll 1
    for (int ch = 0; ch < 16; ch++) {
        CP_WAIT2();
        __syncthreads();
        if (ch + 3 < 16) {
            load_stage(sm0 + ((ch + 3) & 3) * STAGE_B,
                       a_hi + (ch + 3) * 32, a_lo + (ch + 3) * 32,
                       b_hi + (ch + 3) * 32, b_lo + (ch + 3) * 32, I_, I_, tid);
        }
        CP_COMMIT();
        compute_chunk(sm0 + (ch & 3) * STAGE_B, wid, lane, acc);
    }

    // epilogue: + bias, scatter to pre[t][b][j']
    const int wm = (wid >> 1) * 32;
    const int wn = (wid & 1) * 32;
    const int qr = lane >> 2, qc = 2 * (lane & 3);
#pragma unroll
    for (int mt = 0; mt < 2; mt++) {
#pragma unroll
        for (int half = 0; half < 2; half++) {
            int r = wm + mt * 16 + qr + half * 8;
            int m = mb + r;
            int b = m >> 9, tt = m & 511;
            float* preh = (tt < 256 ? g_pre0 : g_pre1);
            float* dst = preh + (size_t)(tt & 255) * B_ * G_ + (size_t)b * G_ + cb;
#pragma unroll
            for (int nt = 0; nt < 4; nt++) {
                int col = wn + nt * 8 + qc;
                dst[col]     = acc[mt][nt][half * 2 + 0] + g_biasp[cb + col];
                dst[col + 1] = acc[mt][nt][half * 2 + 1] + g_biasp[cb + col + 1];
            }
        }
    }
}

// ==================== one LSTM step (HMMA, deep pipeline, fused epilogue) ====================
__device__ __forceinline__ float sigm(float v) { return 1.0f / (1.0f + expf(-v)); }

__global__ void __launch_bounds__(256, 1) step_k(float* __restrict__ c, int t) {
    extern __shared__ char smem[];
    const uint32_t sm0 = smem_u32(smem);
    const int tid = threadIdx.x;
    const int wid = tid >> 5, lane = tid & 31;
    const int rb = blockIdx.x * 128;
    const int cb = blockIdx.y * 64;
    const int hb = cb >> 2;

    const __nv_bfloat16* a_hi = g_h_hi[t & 1] + (size_t)rb * H_;
    const __nv_bfloat16* a_lo = g_h_lo[t & 1] + (size_t)rb * H_;
    const __nv_bfloat16* b_hi = g_Whp_hi + (size_t)cb * H_;
    const __nv_bfloat16* b_lo = g_Whp_lo + (size_t)cb * H_;
    __nv_bfloat16* __restrict__ hout_hi = g_h_hi[(t & 1) ^ 1];
    __nv_bfloat16* __restrict__ hout_lo = g_h_lo[(t & 1) ^ 1];

    const float* preh = (t < 256 ? g_pre0 : g_pre1);
    const float* prebase = preh + (size_t)(t & 255) * B_ * G_;

    float acc[2][4][4] = {};

    // ---- prologue: stage 0 group also prefetches pre + c tiles into smem ----
    load_stage(sm0, a_hi, a_lo, b_hi, b_lo, H_, H_, tid);
    {
        // pre tile: 128 rows x 64 fp32 (16 x 16B units per row)
#pragma unroll
        for (int i = 0; i < 8; i++) {
            int u = tid + i * 256;                 // 0..2047
            int r = u >> 4, q = u & 15;
            CP16(sm0 + SM_PRE + (uint32_t)u * 16,
                 prebase + (size_t)(rb + r) * G_ + cb + q * 4);
        }
        // c tile: 128 rows x 16 fp32 (4 x 16B units per row)
#pragma unroll
        for (int i = 0; i < 2; i++) {
            int u = tid + i * 256;                 // 0..511
            int r = u >> 2, q = u & 3;
            CP16(sm0 + SM_C + (uint32_t)u * 16,
                 c + (size_t)(rb + r) * H_ + hb + q * 4);
        }
    }
    CP_COMMIT();
#pragma unroll
    for (int s = 1; s < 3; s++) {
        load_stage(sm0 + s * STAGE_B, a_hi + s * 32, a_lo + s * 32,
                   b_hi + s * 32, b_lo + s * 32, H_, H_, tid);
        CP_COMMIT();
    }

    // ---- mainloop: one barrier per chunk, loads 3 chunks ahead ----
#pragma unroll 1
    for (int ch = 0; ch < 32; ch++) {
        CP_WAIT2();
        __syncthreads();
        if (ch + 3 < 32) {
            load_stage(sm0 + ((ch + 3) & 3) * STAGE_B,
                       a_hi + (ch + 3) * 32, a_lo + (ch + 3) * 32,
                       b_hi + (ch + 3) * 32, b_lo + (ch + 3) * 32, H_, H_, tid);
        }
        CP_COMMIT();
        compute_chunk(sm0 + (ch & 3) * STAGE_B, wid, lane, acc);
    }

    // ---- park gates in smem (reuses stages 0/1, free by now) ----
    float* Gs = (float*)smem;
    const int wm = (wid >> 1) * 32;
    const int wn = (wid & 1) * 32;
    const int qr = lane >> 2, qc = 2 * (lane & 3);
#pragma unroll
    for (int mt = 0; mt < 2; mt++)
#pragma unroll
        for (int nt = 0; nt < 4; nt++) {
            int r0 = wm + mt * 16 + qr;
            int cc = wn + nt * 8 + qc;
            Gs[r0 * 68 + cc]           = acc[mt][nt][0];
            Gs[r0 * 68 + cc + 1]       = acc[mt][nt][1];
            Gs[(r0 + 8) * 68 + cc]     = acc[mt][nt][2];
            Gs[(r0 + 8) * 68 + cc + 1] = acc[mt][nt][3];
        }
    __syncthreads();

    // ---- activations + state update, all operands in smem ----
    const float4* PreS = (const float4*)(smem + SM_PRE);   // [128][16] float4
    const float*  CS   = (const float*)(smem + SM_C);      // [128][16]
#pragma unroll
    for (int it = tid; it < 128 * 16; it += 256) {
        int r = it >> 4, hh = it & 15;
        float4 g = *(const float4*)&Gs[r * 68 + hh * 4];
        float4 p = PreS[r * 16 + hh];
        float iv = sigm(g.x + p.x);
        float fv = sigm(g.y + p.y);
        float gv = tanhf(g.z + p.z);
        float ov = sigm(g.w + p.w);
        size_t idx = (size_t)(rb + r) * H_ + hb + hh;
        float cn = fv * CS[r * 16 + hh] + iv * gv;
        c[idx] = cn;
        float hn = ov * tanhf(cn);
        __nv_bfloat16 hi = __float2bfloat16_rn(hn);
        hout_hi[idx] = hi;
        hout_lo[idx] = __float2bfloat16_rn(hn - __bfloat162float(hi));
    }
}

// ==================== launch ====================
extern "C" void kernel_launch(void* const* d_in, const int* in_sizes, int n_in,
                              void* d_out, int out_size) {
    const float* x  = (const float*)d_in[0];
    const float* Wi = (const float*)d_in[1];
    const float* Wh = (const float*)d_in[2];
    const float* bi = (const float*)d_in[3];
    const float* bh = (const float*)d_in[4];
    const float* c0 = (const float*)d_in[5];
    float* c = (float*)d_out;

    static bool attr_set = false;
    if (!attr_set) {
        cudaFuncSetAttribute(pregemm_k, cudaFuncAttributeMaxDynamicSharedMemorySize, SMEM_BYTES);
        cudaFuncSetAttribute(step_k,    cudaFuncAttributeMaxDynamicSharedMemorySize, SMEM_BYTES);
        attr_set = true;
    }

    cudaMemcpyAsync(c, c0, sizeof(float) * B_ * H_, cudaMemcpyDeviceToDevice);

    split_x_k<<<4096, 256>>>(x);
    permute_init_k<<<512, 256>>>(Wi, Wh, bi, bh);

    pregemm_k<<<dim3((B_ * T_) / 128, G_ / 64), 256, SMEM_BYTES>>>();

    for (int t = 0; t < T_; t++) {
        step_k<<<dim3(B_ / 128, G_ / 64), 256, SMEM_BYTES>>>(c, t);
    }
}